// round 5
// baseline (speedup 1.0000x reference)
#include <cuda_runtime.h>

#define TPB 128
#define XPAD 63   // odd stride: t*63 mod 32 is a bijection -> conflict-free per-thread LDS.32

typedef unsigned long long ull;

// ---- packed fp32x2 helpers (FFMA2 via PTX fma.rn.f32x2) ----
__device__ __forceinline__ ull pk(float lo, float hi) {
    ull r; asm("mov.b64 %0, {%1, %2};" : "=l"(r) : "f"(lo), "f"(hi)); return r;
}
__device__ __forceinline__ float lo2(ull v) { return __uint_as_float((unsigned)v); }
__device__ __forceinline__ float hi2(ull v) { return __uint_as_float((unsigned)(v >> 32)); }
__device__ __forceinline__ ull fma2(ull a, ull b, ull c) {
    ull d; asm("fma.rn.f32x2 %0, %1, %2, %3;" : "=l"(d) : "l"(a), "l"(b), "l"(c)); return d;
}
__device__ __forceinline__ float ex2(float x) {
    float r; asm("ex2.approx.f32 %0, %1;" : "=f"(r) : "f"(x)); return r;
}

// One thread = one batch problem.
// S_ij * log2(e) = x_i^T M x_j + x_i.u + r.x_j + c   (M,u,r,c pre-scaled by log2e)
// out_i = sum_j 2^{S'_ij} vsum_j / sum_j 2^{S'_ij},  vsum_j = wv.x_j + cv
// Two passes over key-pair groups {0,1,2} and {3,4} to shrink live registers -> 5 CTAs/SM.
//
// smem constant layout (duplicated float2 pairs, directly usable as fma2 operands):
// [0..35] M (a*6+d), [36..41] u, [42..47] r, [48..53] wv, [54] c, [55] cv
__global__ __launch_bounds__(TPB, 5) void attn_kernel(
    const float* __restrict__ x,
    const float* __restrict__ Wk, const float* __restrict__ bk,
    const float* __restrict__ Wq, const float* __restrict__ bq,
    const float* __restrict__ Wv, const float* __restrict__ bv,
    float* __restrict__ out)
{
    __shared__ float2 cst[56];
    __shared__ float  xs[TPB * XPAD];
    const int t = threadIdx.x;

    // ---- per-block precompute of dup-packed constants (L2-cached W reads) ----
    if (t < 56) {
        const float L2E = 1.4426950408889634f;
        float s = 0.f;
        if (t < 36) {                    // M[a][b] = sum_e Wq[e][a] Wk[e][b]  (*L2E)
            int a = t / 6, b = t % 6;
            #pragma unroll
            for (int e = 0; e < 6; e++) s += Wq[e*6 + a] * Wk[e*6 + b];
            s *= L2E;
        } else if (t < 42) {             // u[a] = sum_e Wq[e][a] bk[e]  (*L2E)
            int a = t - 36;
            #pragma unroll
            for (int e = 0; e < 6; e++) s += Wq[e*6 + a] * bk[e];
            s *= L2E;
        } else if (t < 48) {             // r[b] = sum_e bq[e] Wk[e][b]  (*L2E)
            int b = t - 42;
            #pragma unroll
            for (int e = 0; e < 6; e++) s += bq[e] * Wk[e*6 + b];
            s *= L2E;
        } else if (t < 54) {             // wv[d] = colsum(Wv)
            int d = t - 48;
            #pragma unroll
            for (int e = 0; e < 6; e++) s += Wv[e*6 + d];
        } else if (t == 54) {            // c = bq.bk (*L2E)
            #pragma unroll
            for (int e = 0; e < 6; e++) s += bq[e] * bk[e];
            s *= L2E;
        } else {                         // cv = sum(bv)
            #pragma unroll
            for (int e = 0; e < 6; e++) s += bv[e];
        }
        cst[t] = make_float2(s, s);
    }

    // ---- coalesced staging: 128 problems * 60 floats, scalar scatter (XPAD odd) ----
    const float4* xg = (const float4*)(x + (size_t)blockIdx.x * (TPB * 60));
    #pragma unroll
    for (int i = 0; i < 15; i++) {
        float4 v = xg[i * TPB + t];
        int g = (i * TPB + t) * 4;       // 60 % 4 == 0 -> float4 never crosses a problem
        int b = g / 60, e = g % 60;
        float* dst = &xs[b * XPAD + e];
        dst[0] = v.x; dst[1] = v.y; dst[2] = v.z; dst[3] = v.w;
    }
    __syncthreads();

    const float* xp = &xs[t * XPAD];
    const ull*   C  = reinterpret_cast<const ull*>(cst);

    float num[10], den[10];
    #pragma unroll
    for (int i = 0; i < 10; i++) { num[i] = 0.f; den[i] = 0.f; }

    // ---- two passes over key-pair groups: {jp=0,1,2} then {jp=3,4} ----
    #pragma unroll
    for (int grp = 0; grp < 2; grp++) {
        const int jp0 = (grp == 0) ? 0 : 3;
        const int NJ  = (grp == 0) ? 3 : 2;

        ull G[6][3], hp[3], vp[3];

        {   // d = 0: fold init (c-operand = u/c/cv) into the first fma2
            ull xx[3];
            #pragma unroll
            for (int jj = 0; jj < NJ; jj++)
                xx[jj] = pk(xp[(jp0+jj)*12 + 0], xp[(jp0+jj)*12 + 6 + 0]);
            #pragma unroll
            for (int a = 0; a < 6; a++) {
                ull m = C[a*6 + 0], u = C[36 + a];
                #pragma unroll
                for (int jj = 0; jj < NJ; jj++) G[a][jj] = fma2(m, xx[jj], u);
            }
            ull r = C[42], w = C[48], c0 = C[54], cv = C[55];
            #pragma unroll
            for (int jj = 0; jj < NJ; jj++) {
                hp[jj] = fma2(r, xx[jj], c0);
                vp[jj] = fma2(w, xx[jj], cv);
            }
        }
        #pragma unroll
        for (int d = 1; d < 6; d++) {
            ull xx[3];
            #pragma unroll
            for (int jj = 0; jj < NJ; jj++)
                xx[jj] = pk(xp[(jp0+jj)*12 + d], xp[(jp0+jj)*12 + 6 + d]);
            #pragma unroll
            for (int a = 0; a < 6; a++) {
                ull m = C[a*6 + d];
                #pragma unroll
                for (int jj = 0; jj < NJ; jj++) G[a][jj] = fma2(m, xx[jj], G[a][jj]);
            }
            ull r = C[42 + d], w = C[48 + d];
            #pragma unroll
            for (int jj = 0; jj < NJ; jj++) {
                hp[jj] = fma2(r, xx[jj], hp[jj]);
                vp[jj] = fma2(w, xx[jj], vp[jj]);
            }
        }

        // phase 2 for this group: accumulate per-query num/den
        #pragma unroll
        for (int i = 0; i < 10; i++) {
            ull X[6];
            #pragma unroll
            for (int a = 0; a < 6; a++) { float xv = xp[i*6 + a]; X[a] = pk(xv, xv); }
            #pragma unroll
            for (int jj = 0; jj < NJ; jj++) {
                ull s = hp[jj];
                #pragma unroll
                for (int a = 0; a < 6; a++) s = fma2(X[a], G[a][jj], s);
                float ea = ex2(lo2(s));
                float eb = ex2(hi2(s));
                num[i] = __fmaf_rn(ea, lo2(vp[jj]), num[i]);
                num[i] = __fmaf_rn(eb, hi2(vp[jj]), num[i]);
                den[i] += ea + eb;
            }
        }
    }

    // ---- divide + output: 5 x float2 per thread ----
    float2* op = (float2*)(out + (size_t)(blockIdx.x * TPB + t) * 10);
    #pragma unroll
    for (int p = 0; p < 5; p++) {
        float r0 = __fdividef(num[2*p],     den[2*p]);
        float r1 = __fdividef(num[2*p + 1], den[2*p + 1]);
        op[p] = make_float2(r0, r1);
    }
}

extern "C" void kernel_launch(void* const* d_in, const int* in_sizes, int n_in,
                              void* d_out, int out_size) {
    const float* x  = (const float*)d_in[0];
    const float* Wk = (const float*)d_in[1];
    const float* bk = (const float*)d_in[2];
    const float* Wq = (const float*)d_in[3];
    const float* bq = (const float*)d_in[4];
    const float* Wv = (const float*)d_in[5];
    const float* bv = (const float*)d_in[6];
    int B = in_sizes[0] / 60;            // 524288
    int blocks = B / TPB;                // 4096
    attn_kernel<<<blocks, TPB>>>(x, Wk, bk, Wq, bq, Wv, bv, (float*)d_out);
}